// round 1
// baseline (speedup 1.0000x reference)
#include <cuda_runtime.h>
#include <cuda_bf16.h>
#include <mma.h>
#include <cstdint>

using namespace nvcuda;

#define B_DIM 4096
#define IN_DIM 2048
#define F_DIM 4096

// Scratch (device globals: no allocation allowed)
__device__ float       g_xr[B_DIM * IN_DIM];          // rotated activations (unnormalized)
__device__ float       g_wr[IN_DIM * F_DIM];          // rotated weights (unnormalized)
__device__ signed char g_xq[B_DIM * IN_DIM];          // int8 quantized activations
__device__ signed char g_wq[IN_DIM * F_DIM];          // int8 quantized weights
__device__ float       g_yr[B_DIM * F_DIM];           // GEMM result; first written as int32, converted in place
__device__ int         g_maxx_bits;
__device__ int         g_maxw_bits;

// ---------------------------------------------------------------------------
// In-register WHT of 64 elements (6 butterfly stages, fully unrolled)
// ---------------------------------------------------------------------------
__device__ __forceinline__ void wht64(float v[64]) {
#pragma unroll
    for (int s = 1; s < 64; s <<= 1) {
#pragma unroll
        for (int i = 0; i < 64; i++) {
            if ((i & s) == 0) {
                float a = v[i], b = v[i + s];
                v[i]     = a + b;
                v[i + s] = a - b;
            }
        }
    }
}

__global__ void init_kernel() {
    g_maxx_bits = 0;
    g_maxw_bits = 0;
}

// ---------------------------------------------------------------------------
// Column-axis WHT pass (transform along rows dimension, i.e. axis 0).
// WHT-4096 over row index r factorizes as WHT-64 over low 6 bits (STRIDE=1)
// composed with WHT-64 over high 6 bits (STRIDE=64).
// One thread owns one (group, column): 64 strided, per-instruction-coalesced loads.
// ---------------------------------------------------------------------------
template <int STRIDE, bool DO_MAX, bool FINAL>
__global__ __launch_bounds__(256) void colwht_kernel(const float* __restrict__ in,
                                                     float* __restrict__ out,
                                                     int ncols,
                                                     const float* __restrict__ bias) {
    int gtid = blockIdx.x * blockDim.x + threadIdx.x;
    int col  = gtid % ncols;
    int q    = gtid / ncols;          // 0..63
    int base = (STRIDE == 1) ? (q << 6) : q;

    float v[64];
#pragma unroll
    for (int b = 0; b < 64; b++) {
        int r = base + b * STRIDE;
        v[b]  = in[r * ncols + col];
    }
    wht64(v);

    if (DO_MAX) {
        float m = 0.f;
#pragma unroll
        for (int b = 0; b < 64; b++) m = fmaxf(m, fabsf(v[b]));
#pragma unroll
        for (int off = 16; off; off >>= 1)
            m = fmaxf(m, __shfl_xor_sync(0xffffffffu, m, off));
        if ((threadIdx.x & 31) == 0) atomicMax(&g_maxx_bits, __float_as_int(m));
    }

    float scale = 1.f, bv = 0.f;
    if (FINAL) {
        float mx = __int_as_float(g_maxx_bits);
        float mw = __int_as_float(g_maxw_bits);
        // sx*sw / 4096 with unnormalized maxima: (mx/127)*(mw/127)*2^-24
        scale = (mx / 127.f) * (mw / 127.f) * 0x1p-24f;
        bv    = bias[col];
    }
#pragma unroll
    for (int b = 0; b < 64; b++) {
        int r = base + b * STRIDE;
        out[r * ncols + col] = FINAL ? (v[b] * scale + bv) : v[b];
    }
}

// ---------------------------------------------------------------------------
// Row-axis WHT (transform along contiguous dim of length 4096).
// 2 rows per block (128 threads, 64 per row). Pass 1: WHT-64 over high bits
// (regs), XOR-swizzled smem transpose, pass 2: WHT-64 over low bits (regs).
// Optional int32->float conversion on input (GEMM output) and max reduction.
// ---------------------------------------------------------------------------
template <bool IN_IS_INT, bool DO_MAXW>
__global__ __launch_bounds__(128) void rowwht_kernel(const void* __restrict__ in_v,
                                                     float* __restrict__ out) {
    __shared__ float sm[2][4096];     // 32 KB
    int g   = threadIdx.x >> 6;       // row within block
    int t   = threadIdx.x & 63;
    int row = blockIdx.x * 2 + g;
    const float* inf = (const float*)in_v;
    const int*   ini = (const int*)in_v;

    float v[64];
#pragma unroll
    for (int k = 0; k < 64; k++) {    // elements t + 64k: transform over high bits
        int idx = t + (k << 6);
        v[k] = IN_IS_INT ? (float)ini[row * 4096 + idx] : inf[row * 4096 + idx];
    }
    wht64(v);
#pragma unroll
    for (int k = 0; k < 64; k++) {
        int a  = t + (k << 6);
        int ph = a ^ ((a >> 6) & 31); // bank-conflict-free swizzle
        sm[g][ph] = v[k];
    }
    __syncthreads();
#pragma unroll
    for (int k = 0; k < 64; k++) {    // elements 64t + k: transform over low bits
        int a  = (t << 6) + k;
        int ph = a ^ ((a >> 6) & 31);
        v[k] = sm[g][ph];
    }
    wht64(v);
#pragma unroll
    for (int k = 0; k < 64; k++) out[row * 4096 + (t << 6) + k] = v[k];

    if (DO_MAXW) {
        float m = 0.f;
#pragma unroll
        for (int k = 0; k < 64; k++) m = fmaxf(m, fabsf(v[k]));
#pragma unroll
        for (int off = 16; off; off >>= 1)
            m = fmaxf(m, __shfl_xor_sync(0xffffffffu, m, off));
        if ((threadIdx.x & 31) == 0) atomicMax(&g_maxw_bits, __float_as_int(m));
    }
}

// ---------------------------------------------------------------------------
// Stochastic quantization to int8 (matches reference arithmetic).
// WHICH: 0 -> use g_maxx_bits, 1 -> use g_maxw_bits
// ---------------------------------------------------------------------------
template <int WHICH>
__global__ __launch_bounds__(256) void quant_kernel(const float* __restrict__ xr,
                                                    const float* __restrict__ noise,
                                                    signed char* __restrict__ qo,
                                                    int n4) {
    int i = blockIdx.x * blockDim.x + threadIdx.x;
    if (i >= n4) return;
    float mv = __int_as_float(WHICH == 0 ? g_maxx_bits : g_maxw_bits);
    float s  = mv / 127.f;

    float4 x  = ((const float4*)xr)[i];
    float4 nz = ((const float4*)noise)[i];

    auto qf = [&](float xv, float nv) -> signed char {
        float xs = xv / s;
        float f  = floorf(xs);
        float q  = f + ((nv < xs - f) ? 1.f : 0.f);
        q = fminf(127.f, fmaxf(-127.f, q));
        return (signed char)(int)q;
    };
    char4 o;
    o.x = qf(x.x, nz.x);
    o.y = qf(x.y, nz.y);
    o.z = qf(x.z, nz.z);
    o.w = qf(x.w, nz.w);
    ((char4*)qo)[i] = o;
}

// ---------------------------------------------------------------------------
// int8 GEMM via WMMA (IMMA): C[int32] = A[4096x2048] * B[2048x4096]
// Block tile 128x128, K-tile 64, 8 warps (4x2), warp tile 32x64.
// ---------------------------------------------------------------------------
#define GBM 128
#define GBN 128
#define GBK 64

__global__ __launch_bounds__(256) void gemm_s8_kernel(const signed char* __restrict__ A,
                                                      const signed char* __restrict__ B,
                                                      int* __restrict__ C) {
    __shared__ __align__(16) signed char As[GBM][GBK];  // 8 KB
    __shared__ __align__(16) signed char Bs[GBK][GBN];  // 8 KB
    const int M = B_DIM, N = F_DIM, K = IN_DIM;
    (void)M;
    int bm   = blockIdx.y * GBM;
    int bn   = blockIdx.x * GBN;
    int tid  = threadIdx.x;
    int warp = tid >> 5;
    int wm   = (warp >> 1) * 32;  // 4 warps along M
    int wn   = (warp & 1) * 64;   // 2 warps along N

    wmma::fragment<wmma::accumulator, 16, 16, 16, int> acc[2][4];
#pragma unroll
    for (int i = 0; i < 2; i++)
#pragma unroll
        for (int j = 0; j < 4; j++) wmma::fill_fragment(acc[i][j], 0);

    for (int k0 = 0; k0 < K; k0 += GBK) {
#pragma unroll
        for (int l = 0; l < 2; l++) {           // A tile: 512 x int4
            int idx = tid + l * 256;
            int row = idx >> 2;
            int c   = (idx & 3) << 4;
            *(int4*)&As[row][c] = *(const int4*)&A[(bm + row) * K + k0 + c];
        }
#pragma unroll
        for (int l = 0; l < 2; l++) {           // B tile: 512 x int4
            int idx = tid + l * 256;
            int row = idx >> 3;
            int c   = (idx & 7) << 4;
            *(int4*)&Bs[row][c] = *(const int4*)&B[(k0 + row) * N + bn + c];
        }
        __syncthreads();
#pragma unroll
        for (int kk = 0; kk < GBK; kk += 16) {
            wmma::fragment<wmma::matrix_a, 16, 16, 16, signed char, wmma::row_major> af[2];
            wmma::fragment<wmma::matrix_b, 16, 16, 16, signed char, wmma::row_major> bf[4];
#pragma unroll
            for (int i = 0; i < 2; i++)
                wmma::load_matrix_sync(af[i], &As[wm + i * 16][kk], GBK);
#pragma unroll
            for (int j = 0; j < 4; j++)
                wmma::load_matrix_sync(bf[j], &Bs[kk][wn + j * 16], GBN);
#pragma unroll
            for (int i = 0; i < 2; i++)
#pragma unroll
                for (int j = 0; j < 4; j++)
                    wmma::mma_sync(acc[i][j], af[i], bf[j], acc[i][j]);
        }
        __syncthreads();
    }
#pragma unroll
    for (int i = 0; i < 2; i++)
#pragma unroll
        for (int j = 0; j < 4; j++)
            wmma::store_matrix_sync(&C[(bm + wm + i * 16) * N + bn + wn + j * 16],
                                    acc[i][j], N, wmma::mem_row_major);
}

// ---------------------------------------------------------------------------
// Host launcher
// ---------------------------------------------------------------------------
extern "C" void kernel_launch(void* const* d_in, const int* in_sizes, int n_in,
                              void* d_out, int out_size) {
    const float* x       = (const float*)d_in[0];  // [4096, 2048]
    const float* w       = (const float*)d_in[1];  // [2048, 4096]
    const float* bias    = (const float*)d_in[2];  // [4096]
    // d_in[3] = h1, d_in[4] = h2 : known Sylvester Hadamard, computed via FWHT
    const float* noise_x = (const float*)d_in[5];  // [4096, 2048]
    const float* noise_w = (const float*)d_in[6];  // [2048, 4096]
    float* out = (float*)d_out;                    // [4096, 4096]

    float*       xr_p = nullptr;
    float*       wr_p = nullptr;
    signed char* xq_p = nullptr;
    signed char* wq_p = nullptr;
    float*       yr_p = nullptr;
    cudaGetSymbolAddress((void**)&xr_p, g_xr);
    cudaGetSymbolAddress((void**)&wr_p, g_wr);
    cudaGetSymbolAddress((void**)&xq_p, g_xq);
    cudaGetSymbolAddress((void**)&wq_p, g_wq);
    cudaGetSymbolAddress((void**)&yr_p, g_yr);

    init_kernel<<<1, 1>>>();

    // xr = WHT_batch(x)  (unnormalized), fused max on second pass
    colwht_kernel<1, false, false><<<(64 * IN_DIM) / 256, 256>>>(x, xr_p, IN_DIM, nullptr);
    colwht_kernel<64, true, false><<<(64 * IN_DIM) / 256, 256>>>(xr_p, xr_p, IN_DIM, nullptr);
    quant_kernel<0><<<(B_DIM * IN_DIM / 4 + 255) / 256, 256>>>(xr_p, noise_x, xq_p,
                                                               B_DIM * IN_DIM / 4);

    // wr = WHT_features(w) (rows of length 4096), fused max
    rowwht_kernel<false, true><<<IN_DIM / 2, 128>>>(w, wr_p);
    quant_kernel<1><<<(IN_DIM * F_DIM / 4 + 255) / 256, 256>>>(wr_p, noise_w, wq_p,
                                                               IN_DIM * F_DIM / 4);

    // exact int8 GEMM -> int32 in g_yr
    gemm_s8_kernel<<<dim3(F_DIM / GBN, B_DIM / GBM), 256>>>(xq_p, wq_p, (int*)yr_p);

    // inverse rotations: WHT along features (rows), then along batch (cols)
    rowwht_kernel<true, false><<<B_DIM / 2, 128>>>(yr_p, yr_p);
    colwht_kernel<1, false, false><<<(64 * F_DIM) / 256, 256>>>(yr_p, yr_p, F_DIM, nullptr);
    // last pass fuses the scale (sx*sw/4096) and bias add, writes d_out
    colwht_kernel<64, false, true><<<(64 * F_DIM) / 256, 256>>>(yr_p, out, F_DIM, bias);
}

// round 3
// speedup vs baseline: 1.8091x; 1.8091x over previous
#include <cuda_runtime.h>
#include <cuda_bf16.h>
#include <cstdint>

#define B_DIM 4096
#define IN_DIM 2048
#define F_DIM 4096

// ---------------------------------------------------------------------------
// Scratch (device globals: no allocation allowed)
// ---------------------------------------------------------------------------
__device__ float       g_xr[B_DIM * IN_DIM];    // rotated activations (unnormalized)
__device__ float       g_wr[IN_DIM * F_DIM];    // rotated weights (unnormalized)
__device__ signed char g_xq[B_DIM * IN_DIM];    // int8 quantized activations [M][K]
__device__ signed char g_wqT[F_DIM * IN_DIM];   // int8 quantized weights TRANSPOSED [N][K]
__device__ float       g_yr[B_DIM * F_DIM];     // GEMM result (float, exact ints)
__device__ int         g_maxx_bits;
__device__ int         g_maxw_bits;

// ===========================================================================
// Helpers
// ===========================================================================
__device__ __forceinline__ uint32_t smem_u32(const void* p) {
    uint32_t a;
    asm("{ .reg .u64 t; cvta.to.shared.u64 t, %1; cvt.u32.u64 %0, t; }" : "=r"(a) : "l"(p));
    return a;
}

__device__ __forceinline__ void cpasync16(uint32_t dst, const void* src) {
    asm volatile("cp.async.cg.shared.global [%0], [%1], 16;\n" :: "r"(dst), "l"(src));
}

// Swizzle<3,4,3>: XOR 16B-chunk index bits [6:4] with 128B-line bits [9:7]
__device__ __forceinline__ uint32_t swz(uint32_t o) { return o ^ (((o >> 7) & 7) << 4); }

__device__ __forceinline__ void ldsm_x4(uint32_t r[4], uint32_t addr) {
    asm volatile("ldmatrix.sync.aligned.m8n8.x4.shared.b16 {%0,%1,%2,%3}, [%4];"
                 : "=r"(r[0]), "=r"(r[1]), "=r"(r[2]), "=r"(r[3]) : "r"(addr));
}

__device__ __forceinline__ void mma_s8(int c[4], const uint32_t a[4], uint32_t b0, uint32_t b1) {
    asm volatile(
        "mma.sync.aligned.m16n8k32.row.col.s32.s8.s8.s32 "
        "{%0,%1,%2,%3}, {%4,%5,%6,%7}, {%8,%9}, {%0,%1,%2,%3};"
        : "+r"(c[0]), "+r"(c[1]), "+r"(c[2]), "+r"(c[3])
        : "r"(a[0]), "r"(a[1]), "r"(a[2]), "r"(a[3]), "r"(b0), "r"(b1));
}

// ===========================================================================
// WHT kernels
// ===========================================================================
__device__ __forceinline__ void wht64(float v[64]) {
#pragma unroll
    for (int s = 1; s < 64; s <<= 1) {
#pragma unroll
        for (int i = 0; i < 64; i++) {
            if ((i & s) == 0) {
                float a = v[i], b = v[i + s];
                v[i]     = a + b;
                v[i + s] = a - b;
            }
        }
    }
}

__global__ void init_kernel() {
    g_maxx_bits = 0;
    g_maxw_bits = 0;
}

template <int STRIDE, bool DO_MAX, bool FINAL>
__global__ __launch_bounds__(256) void colwht_kernel(const float* __restrict__ in,
                                                     float* __restrict__ out,
                                                     int ncols,
                                                     const float* __restrict__ bias) {
    int gtid = blockIdx.x * blockDim.x + threadIdx.x;
    int col  = gtid % ncols;
    int q    = gtid / ncols;
    int base = (STRIDE == 1) ? (q << 6) : q;

    float v[64];
#pragma unroll
    for (int b = 0; b < 64; b++) v[b] = in[(base + b * STRIDE) * ncols + col];
    wht64(v);

    if (DO_MAX) {
        float m = 0.f;
#pragma unroll
        for (int b = 0; b < 64; b++) m = fmaxf(m, fabsf(v[b]));
#pragma unroll
        for (int off = 16; off; off >>= 1)
            m = fmaxf(m, __shfl_xor_sync(0xffffffffu, m, off));
        if ((threadIdx.x & 31) == 0) atomicMax(&g_maxx_bits, __float_as_int(m));
    }

    float scale = 1.f, bv = 0.f;
    if (FINAL) {
        float mx = __int_as_float(g_maxx_bits);
        float mw = __int_as_float(g_maxw_bits);
        scale = (mx / 127.f) * (mw / 127.f) * 0x1p-24f;
        bv    = bias[col];
    }
#pragma unroll
    for (int b = 0; b < 64; b++) {
        int r = base + b * STRIDE;
        out[r * ncols + col] = FINAL ? (v[b] * scale + bv) : v[b];
    }
}

template <bool DO_MAXW>
__global__ __launch_bounds__(128) void rowwht_kernel(const float* __restrict__ in,
                                                     float* __restrict__ out) {
    __shared__ float sm[2][4096];
    int g   = threadIdx.x >> 6;
    int t   = threadIdx.x & 63;
    int row = blockIdx.x * 2 + g;

    float v[64];
#pragma unroll
    for (int k = 0; k < 64; k++) v[k] = in[row * 4096 + t + (k << 6)];
    wht64(v);
#pragma unroll
    for (int k = 0; k < 64; k++) {
        int a  = t + (k << 6);
        int ph = a ^ ((a >> 6) & 31);
        sm[g][ph] = v[k];
    }
    __syncthreads();
#pragma unroll
    for (int k = 0; k < 64; k++) {
        int a  = (t << 6) + k;
        int ph = a ^ ((a >> 6) & 31);
        v[k] = sm[g][ph];
    }
    wht64(v);
#pragma unroll
    for (int k = 0; k < 64; k++) out[row * 4096 + (t << 6) + k] = v[k];

    if (DO_MAXW) {
        float m = 0.f;
#pragma unroll
        for (int k = 0; k < 64; k++) m = fmaxf(m, fabsf(v[k]));
#pragma unroll
        for (int off = 16; off; off >>= 1)
            m = fmaxf(m, __shfl_xor_sync(0xffffffffu, m, off));
        if ((threadIdx.x & 31) == 0) atomicMax(&g_maxw_bits, __float_as_int(m));
    }
}

// ===========================================================================
// Quantization (int8 outputs)
// ===========================================================================
__device__ __forceinline__ float stoch_q(float xv, float nv, float s) {
    float xs = xv / s;
    float f  = floorf(xs);
    float q  = f + ((nv < xs - f) ? 1.f : 0.f);
    return fminf(127.f, fmaxf(-127.f, q));
}

__global__ __launch_bounds__(256) void quantx_kernel(const float* __restrict__ xr,
                                                     const float* __restrict__ noise,
                                                     signed char* __restrict__ qo,
                                                     int n4) {
    int i = blockIdx.x * blockDim.x + threadIdx.x;
    if (i >= n4) return;
    float s = __int_as_float(g_maxx_bits) / 127.f;
    float4 x  = ((const float4*)xr)[i];
    float4 nz = ((const float4*)noise)[i];
    char4 o;
    o.x = (signed char)(int)stoch_q(x.x, nz.x, s);
    o.y = (signed char)(int)stoch_q(x.y, nz.y, s);
    o.z = (signed char)(int)stoch_q(x.z, nz.z, s);
    o.w = (signed char)(int)stoch_q(x.w, nz.w, s);
    ((char4*)qo)[i] = o;
}

// weights: quantize + transpose [IN][F] -> [F][IN] int8 (K-major B operand)
__global__ __launch_bounds__(256) void quantw_transpose_kernel(const float* __restrict__ wr,
                                                               const float* __restrict__ noise,
                                                               signed char* __restrict__ qoT) {
    __shared__ signed char t[32][33];
    float s = __int_as_float(g_maxw_bits) / 127.f;
    int x  = blockIdx.x * 32 + threadIdx.x;   // F index
    int y0 = blockIdx.y * 32;                 // IN base
#pragma unroll
    for (int j = 0; j < 4; j++) {
        int y   = y0 + threadIdx.y + j * 8;
        int idx = y * F_DIM + x;
        t[threadIdx.y + j * 8][threadIdx.x] = (signed char)(int)stoch_q(wr[idx], noise[idx], s);
    }
    __syncthreads();
#pragma unroll
    for (int j = 0; j < 4; j++) {
        int fo = blockIdx.x * 32 + threadIdx.y + j * 8;
        qoT[(size_t)fo * IN_DIM + y0 + threadIdx.x] = t[threadIdx.x][threadIdx.y + j * 8];
    }
}

// ===========================================================================
// Pipelined int8 GEMM: C(float) = A[4096x2048] @ B^T   (B stored [N][K])
// mma.sync.m16n8k32.s8, CTA 128x128, BK=64, 4-stage cp.async, SW smem.
// ===========================================================================
#define GBM 128
#define GBN 128
#define GBK 64
#define NSTAGE 4
#define KT (IN_DIM / GBK)        // 32
#define STAGE_BYTES (GBM * GBK + GBN * GBK)   // 16384
#define GEMM_SMEM (NSTAGE * STAGE_BYTES)      // 65536

__global__ __launch_bounds__(256, 1) void gemm_s8_kernel(const signed char* __restrict__ A,
                                                         const signed char* __restrict__ Bm,
                                                         float* __restrict__ C) {
    extern __shared__ signed char smem[];
    uint32_t sb = smem_u32(smem);
    int tid = threadIdx.x, warp = tid >> 5, lane = tid & 31;
    int bm = blockIdx.y * GBM, bn = blockIdx.x * GBN;
    int wm = (warp >> 1) * 32, wn = (warp & 1) * 64;

    int acc[2][8][4];
#pragma unroll
    for (int i = 0; i < 2; i++)
#pragma unroll
        for (int j = 0; j < 8; j++)
#pragma unroll
            for (int k = 0; k < 4; k++) acc[i][j][k] = 0;

    auto load_stage = [&](int s, int ki) {
        uint32_t sA = sb + s * STAGE_BYTES;
        uint32_t sB = sA + GBM * GBK;
        int k0 = ki * GBK;
#pragma unroll
        for (int j = 0; j < 2; j++) {
            int c = tid + j * 256;
            int row = c >> 2, cc = c & 3;
            cpasync16(sA + swz(row * 64 + cc * 16),
                      A + (size_t)(bm + row) * IN_DIM + k0 + cc * 16);
        }
#pragma unroll
        for (int j = 0; j < 2; j++) {
            int c = tid + j * 256;
            int row = c >> 2, cc = c & 3;
            cpasync16(sB + swz(row * 64 + cc * 16),
                      Bm + (size_t)(bn + row) * IN_DIM + k0 + cc * 16);
        }
        asm volatile("cp.async.commit_group;\n");
    };

    load_stage(0, 0);
    load_stage(1, 1);
    load_stage(2, 2);

    for (int i = 0; i < KT; i++) {
        if (i > 0) __syncthreads();            // all warps done with buffer (i-1)&3
        if (i + 3 < KT) {
            load_stage((i + 3) & 3, i + 3);    // overwrite buffer (i-1)&3
            asm volatile("cp.async.wait_group 3;\n");   // stage i landed
        } else {
            asm volatile("cp.async.wait_group 0;\n");
        }
        __syncthreads();

        uint32_t sA = sb + (i & 3) * STAGE_BYTES;
        uint32_t sB = sA + GBM * GBK;
        int rl = lane & 15, chh = (lane >> 4) * 16;
#pragma unroll
        for (int ks = 0; ks < 2; ks++) {
            uint32_t a[2][4], b[4][4];
#pragma unroll
            for (int mt = 0; mt < 2; mt++)
                ldsm_x4(a[mt], sA + swz((wm + mt * 16 + rl) * 64 + ks * 32 + chh));
#pragma unroll
            for (int ng = 0; ng < 4; ng++)
                ldsm_x4(b[ng], sB + swz((wn + ng * 16 + rl) * 64 + ks * 32 + chh));
#pragma unroll
            for (int mt = 0; mt < 2; mt++)
#pragma unroll
                for (int ng = 0; ng < 4; ng++) {
                    mma_s8(acc[mt][2 * ng + 0], a[mt], b[ng][0], b[ng][2]);
                    mma_s8(acc[mt][2 * ng + 1], a[mt], b[ng][1], b[ng][3]);
                }
        }
    }

    // Epilogue: int32 -> float (exact), direct stores
    float* outp = C + (size_t)bm * F_DIM + bn;
#pragma unroll
    for (int mt = 0; mt < 2; mt++)
#pragma unroll
        for (int nt = 0; nt < 8; nt++) {
            int row = wm + mt * 16 + (lane >> 2);
            int col = wn + nt * 8 + (lane & 3) * 2;
            float2 v0 = make_float2((float)acc[mt][nt][0], (float)acc[mt][nt][1]);
            float2 v1 = make_float2((float)acc[mt][nt][2], (float)acc[mt][nt][3]);
            *(float2*)&outp[(size_t)row * F_DIM + col]       = v0;
            *(float2*)&outp[(size_t)(row + 8) * F_DIM + col] = v1;
        }
}

// ===========================================================================
// Host launcher
// ===========================================================================
extern "C" void kernel_launch(void* const* d_in, const int* in_sizes, int n_in,
                              void* d_out, int out_size) {
    const float* x       = (const float*)d_in[0];  // [4096, 2048]
    const float* w       = (const float*)d_in[1];  // [2048, 4096]
    const float* bias    = (const float*)d_in[2];  // [4096]
    const float* noise_x = (const float*)d_in[5];  // [4096, 2048]
    const float* noise_w = (const float*)d_in[6];  // [2048, 4096]
    float* out = (float*)d_out;                    // [4096, 4096]

    float*       xr_p = nullptr;
    float*       wr_p = nullptr;
    signed char* xq_p = nullptr;
    signed char* wq_p = nullptr;
    float*       yr_p = nullptr;
    cudaGetSymbolAddress((void**)&xr_p, g_xr);
    cudaGetSymbolAddress((void**)&wr_p, g_wr);
    cudaGetSymbolAddress((void**)&xq_p, g_xq);
    cudaGetSymbolAddress((void**)&wq_p, g_wqT);
    cudaGetSymbolAddress((void**)&yr_p, g_yr);

    cudaFuncSetAttribute(gemm_s8_kernel, cudaFuncAttributeMaxDynamicSharedMemorySize, GEMM_SMEM);

    init_kernel<<<1, 1>>>();

    // xr = WHT_batch(x) (unnormalized), fused max on second pass
    colwht_kernel<1, false, false><<<(64 * IN_DIM) / 256, 256>>>(x, xr_p, IN_DIM, nullptr);
    colwht_kernel<64, true, false><<<(64 * IN_DIM) / 256, 256>>>(xr_p, xr_p, IN_DIM, nullptr);
    quantx_kernel<<<(B_DIM * IN_DIM / 4 + 255) / 256, 256>>>(xr_p, noise_x, xq_p,
                                                             B_DIM * IN_DIM / 4);

    // wr = WHT_features(w), fused max; quantize + transpose to [F][IN]
    rowwht_kernel<true><<<IN_DIM / 2, 128>>>(w, wr_p);
    quantw_transpose_kernel<<<dim3(F_DIM / 32, IN_DIM / 32), dim3(32, 8)>>>(wr_p, noise_w, wq_p);

    // pipelined int8 mma.sync GEMM -> float
    gemm_s8_kernel<<<dim3(F_DIM / GBN, B_DIM / GBM), 256, GEMM_SMEM>>>(xq_p, wq_p, yr_p);

    // inverse rotations: WHT along features (rows), then along batch (cols)
    rowwht_kernel<false><<<B_DIM / 2, 128>>>(yr_p, yr_p);
    colwht_kernel<1, false, false><<<(64 * F_DIM) / 256, 256>>>(yr_p, yr_p, F_DIM, nullptr);
    colwht_kernel<64, false, true><<<(64 * F_DIM) / 256, 256>>>(yr_p, out, F_DIM, bias);
}

// round 4
// speedup vs baseline: 1.8219x; 1.0071x over previous
#include <cuda_runtime.h>
#include <cuda_bf16.h>
#include <cstdint>

#define B_DIM 4096
#define IN_DIM 2048
#define F_DIM 4096

// ---------------------------------------------------------------------------
// Scratch (device globals: no allocation allowed)
// ---------------------------------------------------------------------------
__device__ float       g_xr[B_DIM * IN_DIM];    // rotated activations (unnormalized)
__device__ float       g_wr[IN_DIM * F_DIM];    // rotated weights (unnormalized)
__device__ signed char g_xq[B_DIM * IN_DIM];    // int8 quantized activations [M][K]
__device__ signed char g_wqT[F_DIM * IN_DIM];   // int8 quantized weights TRANSPOSED [N][K]
__device__ float       g_yr[B_DIM * F_DIM];     // GEMM result (float, exact ints)
__device__ int         g_maxx_bits;
__device__ int         g_maxw_bits;

// ===========================================================================
// Helpers
// ===========================================================================
__device__ __forceinline__ uint32_t smem_u32(const void* p) {
    uint32_t a;
    asm("{ .reg .u64 t; cvta.to.shared.u64 t, %1; cvt.u32.u64 %0, t; }" : "=r"(a) : "l"(p));
    return a;
}

__device__ __forceinline__ void cpasync16(uint32_t dst, const void* src) {
    asm volatile("cp.async.cg.shared.global [%0], [%1], 16;\n" :: "r"(dst), "l"(src));
}

// Swizzle<3,4,3>: XOR 16B-chunk index bits [6:4] with 128B-line bits [9:7]
__device__ __forceinline__ uint32_t swz(uint32_t o) { return o ^ (((o >> 7) & 7) << 4); }

__device__ __forceinline__ void ldsm_x4(uint32_t r[4], uint32_t addr) {
    asm volatile("ldmatrix.sync.aligned.m8n8.x4.shared.b16 {%0,%1,%2,%3}, [%4];"
                 : "=r"(r[0]), "=r"(r[1]), "=r"(r[2]), "=r"(r[3]) : "r"(addr));
}

__device__ __forceinline__ void mma_s8(int c[4], const uint32_t a[4], uint32_t b0, uint32_t b1) {
    asm volatile(
        "mma.sync.aligned.m16n8k32.row.col.s32.s8.s8.s32 "
        "{%0,%1,%2,%3}, {%4,%5,%6,%7}, {%8,%9}, {%0,%1,%2,%3};"
        : "+r"(c[0]), "+r"(c[1]), "+r"(c[2]), "+r"(c[3])
        : "r"(a[0]), "r"(a[1]), "r"(a[2]), "r"(a[3]), "r"(b0), "r"(b1));
}

// ===========================================================================
// WHT kernels
// ===========================================================================
__device__ __forceinline__ void wht64(float v[64]) {
#pragma unroll
    for (int s = 1; s < 64; s <<= 1) {
#pragma unroll
        for (int i = 0; i < 64; i++) {
            if ((i & s) == 0) {
                float a = v[i], b = v[i + s];
                v[i]     = a + b;
                v[i + s] = a - b;
            }
        }
    }
}

__global__ void init_kernel() {
    g_maxx_bits = 0;
    g_maxw_bits = 0;
}

template <int STRIDE, bool DO_MAX, bool FINAL>
__global__ __launch_bounds__(256) void colwht_kernel(const float* __restrict__ in,
                                                     float* __restrict__ out,
                                                     int ncols,
                                                     const float* __restrict__ bias) {
    int gtid = blockIdx.x * blockDim.x + threadIdx.x;
    int col  = gtid % ncols;
    int q    = gtid / ncols;
    int base = (STRIDE == 1) ? (q << 6) : q;

    float v[64];
#pragma unroll
    for (int b = 0; b < 64; b++) v[b] = in[(base + b * STRIDE) * ncols + col];
    wht64(v);

    if (DO_MAX) {
        float m = 0.f;
#pragma unroll
        for (int b = 0; b < 64; b++) m = fmaxf(m, fabsf(v[b]));
#pragma unroll
        for (int off = 16; off; off >>= 1)
            m = fmaxf(m, __shfl_xor_sync(0xffffffffu, m, off));
        if ((threadIdx.x & 31) == 0) atomicMax(&g_maxx_bits, __float_as_int(m));
    }

    float scale = 1.f, bv = 0.f;
    if (FINAL) {
        float mx = __int_as_float(g_maxx_bits);
        float mw = __int_as_float(g_maxw_bits);
        scale = (mx / 127.f) * (mw / 127.f) * 0x1p-24f;
        bv    = bias[col];
    }
#pragma unroll
    for (int b = 0; b < 64; b++) {
        int r = base + b * STRIDE;
        out[r * ncols + col] = FINAL ? (v[b] * scale + bv) : v[b];
    }
}

template <bool DO_MAXW>
__global__ __launch_bounds__(128) void rowwht_kernel(const float* __restrict__ in,
                                                     float* __restrict__ out) {
    __shared__ float sm[2][4096];
    int g   = threadIdx.x >> 6;
    int t   = threadIdx.x & 63;
    int row = blockIdx.x * 2 + g;

    float v[64];
#pragma unroll
    for (int k = 0; k < 64; k++) v[k] = in[row * 4096 + t + (k << 6)];
    wht64(v);
#pragma unroll
    for (int k = 0; k < 64; k++) {
        int a  = t + (k << 6);
        int ph = a ^ ((a >> 6) & 31);
        sm[g][ph] = v[k];
    }
    __syncthreads();
#pragma unroll
    for (int k = 0; k < 64; k++) {
        int a  = (t << 6) + k;
        int ph = a ^ ((a >> 6) & 31);
        v[k] = sm[g][ph];
    }
    wht64(v);
#pragma unroll
    for (int k = 0; k < 64; k++) out[row * 4096 + (t << 6) + k] = v[k];

    if (DO_MAXW) {
        float m = 0.f;
#pragma unroll
        for (int k = 0; k < 64; k++) m = fmaxf(m, fabsf(v[k]));
#pragma unroll
        for (int off = 16; off; off >>= 1)
            m = fmaxf(m, __shfl_xor_sync(0xffffffffu, m, off));
        if ((threadIdx.x & 31) == 0) atomicMax(&g_maxw_bits, __float_as_int(m));
    }
}

// ===========================================================================
// Quantization (int8 outputs)
// ===========================================================================
__device__ __forceinline__ float stoch_q(float xv, float nv, float s) {
    float xs = xv / s;
    float f  = floorf(xs);
    float q  = f + ((nv < xs - f) ? 1.f : 0.f);
    return fminf(127.f, fmaxf(-127.f, q));
}

__global__ __launch_bounds__(256) void quantx_kernel(const float* __restrict__ xr,
                                                     const float* __restrict__ noise,
                                                     signed char* __restrict__ qo,
                                                     int n4) {
    int i = blockIdx.x * blockDim.x + threadIdx.x;
    if (i >= n4) return;
    float s = __int_as_float(g_maxx_bits) / 127.f;
    float4 x  = ((const float4*)xr)[i];
    float4 nz = ((const float4*)noise)[i];
    char4 o;
    o.x = (signed char)(int)stoch_q(x.x, nz.x, s);
    o.y = (signed char)(int)stoch_q(x.y, nz.y, s);
    o.z = (signed char)(int)stoch_q(x.z, nz.z, s);
    o.w = (signed char)(int)stoch_q(x.w, nz.w, s);
    ((char4*)qo)[i] = o;
}

// weights: quantize + transpose [IN][F] -> [F][IN] int8 (K-major B operand)
__global__ __launch_bounds__(256) void quantw_transpose_kernel(const float* __restrict__ wr,
                                                               const float* __restrict__ noise,
                                                               signed char* __restrict__ qoT) {
    __shared__ signed char t[32][33];
    float s = __int_as_float(g_maxw_bits) / 127.f;
    int x  = blockIdx.x * 32 + threadIdx.x;   // F index
    int y0 = blockIdx.y * 32;                 // IN base
#pragma unroll
    for (int j = 0; j < 4; j++) {
        int y   = y0 + threadIdx.y + j * 8;
        int idx = y * F_DIM + x;
        t[threadIdx.y + j * 8][threadIdx.x] = (signed char)(int)stoch_q(wr[idx], noise[idx], s);
    }
    __syncthreads();
#pragma unroll
    for (int j = 0; j < 4; j++) {
        int fo = blockIdx.x * 32 + threadIdx.y + j * 8;
        qoT[(size_t)fo * IN_DIM + y0 + threadIdx.x] = t[threadIdx.x][threadIdx.y + j * 8];
    }
}

// ===========================================================================
// Pipelined int8 GEMM: C(float) = A[4096x2048] @ B^T   (B stored [N][K])
// mma.sync.m16n8k32.s8, CTA 128x128, 8 warps (2x4), warp tile 64x32,
// BK=64, 4-stage cp.async, single sync per K-iter, 2 CTAs/SM.
// ===========================================================================
#define GBM 128
#define GBN 128
#define GBK 64
#define NSTAGE 4
#define KT (IN_DIM / GBK)                     // 32
#define STAGE_BYTES (GBM * GBK + GBN * GBK)   // 16384
#define GEMM_SMEM (NSTAGE * STAGE_BYTES)      // 65536

__global__ __launch_bounds__(256, 2) void gemm_s8_kernel(const signed char* __restrict__ A,
                                                         const signed char* __restrict__ Bm,
                                                         float* __restrict__ C) {
    extern __shared__ signed char smem[];
    uint32_t sb = smem_u32(smem);
    int tid = threadIdx.x, warp = tid >> 5, lane = tid & 31;
    int bm = blockIdx.y * GBM, bn = blockIdx.x * GBN;
    int wm = (warp >> 2) * 64;   // 2 warps along M, tile 64
    int wn = (warp & 3) * 32;    // 4 warps along N, tile 32

    int acc[4][4][4];
#pragma unroll
    for (int i = 0; i < 4; i++)
#pragma unroll
        for (int j = 0; j < 4; j++)
#pragma unroll
            for (int k = 0; k < 4; k++) acc[i][j][k] = 0;

    auto load_stage = [&](int s, int ki) {
        uint32_t sA = sb + s * STAGE_BYTES;
        uint32_t sB = sA + GBM * GBK;
        int k0 = ki * GBK;
#pragma unroll
        for (int j = 0; j < 2; j++) {
            int c = tid + j * 256;
            int row = c >> 2, cc = c & 3;
            cpasync16(sA + swz(row * 64 + cc * 16),
                      A + (size_t)(bm + row) * IN_DIM + k0 + cc * 16);
        }
#pragma unroll
        for (int j = 0; j < 2; j++) {
            int c = tid + j * 256;
            int row = c >> 2, cc = c & 3;
            cpasync16(sB + swz(row * 64 + cc * 16),
                      Bm + (size_t)(bn + row) * IN_DIM + k0 + cc * 16);
        }
        asm volatile("cp.async.commit_group;\n");
    };

    load_stage(0, 0);
    load_stage(1, 1);
    load_stage(2, 2);

    int rl = lane & 15, chh = (lane >> 4) * 16;
    for (int i = 0; i < KT; i++) {
        asm volatile("cp.async.wait_group 2;\n");   // stage i landed (per-thread)
        __syncthreads();                            // visible to all; prev reads done
        if (i + 3 < KT) load_stage((i + 3) & 3, i + 3);  // prefetch before compute

        uint32_t sA = sb + (i & 3) * STAGE_BYTES;
        uint32_t sB = sA + GBM * GBK;
#pragma unroll
        for (int ks = 0; ks < 2; ks++) {
            uint32_t a[4][4], b[2][4];
#pragma unroll
            for (int mt = 0; mt < 4; mt++)
                ldsm_x4(a[mt], sA + swz((wm + mt * 16 + rl) * 64 + ks * 32 + chh));
#pragma unroll
            for (int ng = 0; ng < 2; ng++)
                ldsm_x4(b[ng], sB + swz((wn + ng * 16 + rl) * 64 + ks * 32 + chh));
#pragma unroll
            for (int mt = 0; mt < 4; mt++)
#pragma unroll
                for (int ng = 0; ng < 2; ng++) {
                    mma_s8(acc[mt][2 * ng + 0], a[mt], b[ng][0], b[ng][2]);
                    mma_s8(acc[mt][2 * ng + 1], a[mt], b[ng][1], b[ng][3]);
                }
        }
    }

    // Epilogue: int32 -> float (exact), direct stores
    float* outp = C + (size_t)bm * F_DIM + bn;
#pragma unroll
    for (int mt = 0; mt < 4; mt++)
#pragma unroll
        for (int nt = 0; nt < 4; nt++) {
            int row = wm + mt * 16 + (lane >> 2);
            int col = wn + nt * 8 + (lane & 3) * 2;
            float2 v0 = make_float2((float)acc[mt][nt][0], (float)acc[mt][nt][1]);
            float2 v1 = make_float2((float)acc[mt][nt][2], (float)acc[mt][nt][3]);
            *(float2*)&outp[(size_t)row * F_DIM + col]       = v0;
            *(float2*)&outp[(size_t)(row + 8) * F_DIM + col] = v1;
        }
}

// ===========================================================================
// Host launcher
// ===========================================================================
extern "C" void kernel_launch(void* const* d_in, const int* in_sizes, int n_in,
                              void* d_out, int out_size) {
    const float* x       = (const float*)d_in[0];  // [4096, 2048]
    const float* w       = (const float*)d_in[1];  // [2048, 4096]
    const float* bias    = (const float*)d_in[2];  // [4096]
    const float* noise_x = (const float*)d_in[5];  // [4096, 2048]
    const float* noise_w = (const float*)d_in[6];  // [2048, 4096]
    float* out = (float*)d_out;                    // [4096, 4096]

    float*       xr_p = nullptr;
    float*       wr_p = nullptr;
    signed char* xq_p = nullptr;
    signed char* wq_p = nullptr;
    float*       yr_p = nullptr;
    cudaGetSymbolAddress((void**)&xr_p, g_xr);
    cudaGetSymbolAddress((void**)&wr_p, g_wr);
    cudaGetSymbolAddress((void**)&xq_p, g_xq);
    cudaGetSymbolAddress((void**)&wq_p, g_wqT);
    cudaGetSymbolAddress((void**)&yr_p, g_yr);

    cudaFuncSetAttribute(gemm_s8_kernel, cudaFuncAttributeMaxDynamicSharedMemorySize, GEMM_SMEM);

    init_kernel<<<1, 1>>>();

    // xr = WHT_batch(x) (unnormalized), fused max on second pass
    colwht_kernel<1, false, false><<<(64 * IN_DIM) / 256, 256>>>(x, xr_p, IN_DIM, nullptr);
    colwht_kernel<64, true, false><<<(64 * IN_DIM) / 256, 256>>>(xr_p, xr_p, IN_DIM, nullptr);
    quantx_kernel<<<(B_DIM * IN_DIM / 4 + 255) / 256, 256>>>(xr_p, noise_x, xq_p,
                                                             B_DIM * IN_DIM / 4);

    // wr = WHT_features(w), fused max; quantize + transpose to [F][IN]
    rowwht_kernel<true><<<IN_DIM / 2, 128>>>(w, wr_p);
    quantw_transpose_kernel<<<dim3(F_DIM / 32, IN_DIM / 32), dim3(32, 8)>>>(wr_p, noise_w, wq_p);

    // pipelined int8 mma.sync GEMM -> float
    gemm_s8_kernel<<<dim3(F_DIM / GBN, B_DIM / GBM), 256, GEMM_SMEM>>>(xq_p, wq_p, yr_p);

    // inverse rotations: WHT along features (rows), then along batch (cols)
    rowwht_kernel<false><<<B_DIM / 2, 128>>>(yr_p, yr_p);
    colwht_kernel<1, false, false><<<(64 * F_DIM) / 256, 256>>>(yr_p, yr_p, F_DIM, nullptr);
    colwht_kernel<64, false, true><<<(64 * F_DIM) / 256, 256>>>(yr_p, out, F_DIM, bias);
}

// round 5
// speedup vs baseline: 3.0749x; 1.6878x over previous
#include <cuda_runtime.h>
#include <cuda_bf16.h>
#include <cstdint>

#define B_DIM 4096
#define IN_DIM 2048
#define F_DIM 4096

// ---------------------------------------------------------------------------
// Scratch (device globals: no allocation allowed)
// ---------------------------------------------------------------------------
__device__ float          g_xr[B_DIM * IN_DIM];    // rotated activations (unnormalized)
__device__ float          g_wr[IN_DIM * F_DIM];    // rotated weights (unnormalized)
__device__ __nv_bfloat16  g_xq[B_DIM * IN_DIM];    // quantized activations (bf16 ints) [M][K]
__device__ __nv_bfloat16  g_wqT[F_DIM * IN_DIM];   // quantized weights TRANSPOSED [N][K]
__device__ float          g_yr[B_DIM * F_DIM];     // GEMM result (float, exact ints)
__device__ int            g_maxx_bits;
__device__ int            g_maxw_bits;

// ===========================================================================
// Helpers
// ===========================================================================
__device__ __forceinline__ uint32_t smem_u32(const void* p) {
    uint32_t a;
    asm("{ .reg .u64 t; cvta.to.shared.u64 t, %1; cvt.u32.u64 %0, t; }" : "=r"(a) : "l"(p));
    return a;
}

__device__ __forceinline__ void cpasync16(uint32_t dst, const void* src) {
    asm volatile("cp.async.cg.shared.global [%0], [%1], 16;\n" :: "r"(dst), "l"(src));
}

// Swizzle<3,4,3>: XOR 16B-chunk bits [6:4] with 128B-line bits [9:7]
__device__ __forceinline__ uint32_t swz(uint32_t o) { return o ^ (((o >> 7) & 7) << 4); }

__device__ __forceinline__ void ldsm_x4(uint32_t r[4], uint32_t addr) {
    asm volatile("ldmatrix.sync.aligned.m8n8.x4.shared.b16 {%0,%1,%2,%3}, [%4];"
                 : "=r"(r[0]), "=r"(r[1]), "=r"(r[2]), "=r"(r[3]) : "r"(addr));
}

__device__ __forceinline__ void mma_bf16(float c[4], const uint32_t a[4], uint32_t b0, uint32_t b1) {
    asm volatile(
        "mma.sync.aligned.m16n8k16.row.col.f32.bf16.bf16.f32 "
        "{%0,%1,%2,%3}, {%4,%5,%6,%7}, {%8,%9}, {%0,%1,%2,%3};"
        : "+f"(c[0]), "+f"(c[1]), "+f"(c[2]), "+f"(c[3])
        : "r"(a[0]), "r"(a[1]), "r"(a[2]), "r"(a[3]), "r"(b0), "r"(b1));
}

// ===========================================================================
// WHT kernels
// ===========================================================================
__device__ __forceinline__ void wht64(float v[64]) {
#pragma unroll
    for (int s = 1; s < 64; s <<= 1) {
#pragma unroll
        for (int i = 0; i < 64; i++) {
            if ((i & s) == 0) {
                float a = v[i], b = v[i + s];
                v[i]     = a + b;
                v[i + s] = a - b;
            }
        }
    }
}

__global__ void init_kernel() {
    g_maxx_bits = 0;
    g_maxw_bits = 0;
}

template <int STRIDE, bool DO_MAX, bool FINAL>
__global__ __launch_bounds__(256) void colwht_kernel(const float* __restrict__ in,
                                                     float* __restrict__ out,
                                                     int ncols,
                                                     const float* __restrict__ bias) {
    int gtid = blockIdx.x * blockDim.x + threadIdx.x;
    int col  = gtid % ncols;
    int q    = gtid / ncols;
    int base = (STRIDE == 1) ? (q << 6) : q;

    float v[64];
#pragma unroll
    for (int b = 0; b < 64; b++) v[b] = in[(base + b * STRIDE) * ncols + col];
    wht64(v);

    if (DO_MAX) {
        float m = 0.f;
#pragma unroll
        for (int b = 0; b < 64; b++) m = fmaxf(m, fabsf(v[b]));
#pragma unroll
        for (int off = 16; off; off >>= 1)
            m = fmaxf(m, __shfl_xor_sync(0xffffffffu, m, off));
        if ((threadIdx.x & 31) == 0) atomicMax(&g_maxx_bits, __float_as_int(m));
    }

    float scale = 1.f, bv = 0.f;
    if (FINAL) {
        float mx = __int_as_float(g_maxx_bits);
        float mw = __int_as_float(g_maxw_bits);
        scale = (mx / 127.f) * (mw / 127.f) * 0x1p-24f;
        bv    = bias[col];
    }
#pragma unroll
    for (int b = 0; b < 64; b++) {
        int r = base + b * STRIDE;
        out[r * ncols + col] = FINAL ? (v[b] * scale + bv) : v[b];
    }
}

template <bool DO_MAXW>
__global__ __launch_bounds__(128) void rowwht_kernel(const float* __restrict__ in,
                                                     float* __restrict__ out) {
    __shared__ float sm[2][4096];
    int g   = threadIdx.x >> 6;
    int t   = threadIdx.x & 63;
    int row = blockIdx.x * 2 + g;

    float v[64];
#pragma unroll
    for (int k = 0; k < 64; k++) v[k] = in[row * 4096 + t + (k << 6)];
    wht64(v);
#pragma unroll
    for (int k = 0; k < 64; k++) {
        int a  = t + (k << 6);
        int ph = a ^ ((a >> 6) & 31);
        sm[g][ph] = v[k];
    }
    __syncthreads();
#pragma unroll
    for (int k = 0; k < 64; k++) {
        int a  = (t << 6) + k;
        int ph = a ^ ((a >> 6) & 31);
        v[k] = sm[g][ph];
    }
    wht64(v);
#pragma unroll
    for (int k = 0; k < 64; k++) out[row * 4096 + (t << 6) + k] = v[k];

    if (DO_MAXW) {
        float m = 0.f;
#pragma unroll
        for (int k = 0; k < 64; k++) m = fmaxf(m, fabsf(v[k]));
#pragma unroll
        for (int off = 16; off; off >>= 1)
            m = fmaxf(m, __shfl_xor_sync(0xffffffffu, m, off));
        if ((threadIdx.x & 31) == 0) atomicMax(&g_maxw_bits, __float_as_int(m));
    }
}

// ===========================================================================
// Quantization (bf16 integer-valued outputs)
// ===========================================================================
__device__ __forceinline__ float stoch_q(float xv, float nv, float s) {
    float xs = xv / s;
    float f  = floorf(xs);
    float q  = f + ((nv < xs - f) ? 1.f : 0.f);
    return fminf(127.f, fmaxf(-127.f, q));
}

__global__ __launch_bounds__(256) void quantx_kernel(const float* __restrict__ xr,
                                                     const float* __restrict__ noise,
                                                     __nv_bfloat16* __restrict__ qo,
                                                     int n4) {
    int i = blockIdx.x * blockDim.x + threadIdx.x;
    if (i >= n4) return;
    float s = __int_as_float(g_maxx_bits) / 127.f;
    float4 x  = ((const float4*)xr)[i];
    float4 nz = ((const float4*)noise)[i];
    __nv_bfloat162 lo = __floats2bfloat162_rn(stoch_q(x.x, nz.x, s), stoch_q(x.y, nz.y, s));
    __nv_bfloat162 hi = __floats2bfloat162_rn(stoch_q(x.z, nz.z, s), stoch_q(x.w, nz.w, s));
    uint2 o;
    o.x = *(uint32_t*)&lo;
    o.y = *(uint32_t*)&hi;
    ((uint2*)qo)[i] = o;
}

// weights: quantize + transpose [IN][F] -> [F][IN] bf16 (K-major B operand)
__global__ __launch_bounds__(256) void quantw_transpose_kernel(const float* __restrict__ wr,
                                                               const float* __restrict__ noise,
                                                               __nv_bfloat16* __restrict__ qoT) {
    __shared__ __nv_bfloat16 t[32][33];
    float s = __int_as_float(g_maxw_bits) / 127.f;
    int x  = blockIdx.x * 32 + threadIdx.x;   // F index
    int y0 = blockIdx.y * 32;                 // IN base
#pragma unroll
    for (int j = 0; j < 4; j++) {
        int y   = y0 + threadIdx.y + j * 8;
        int idx = y * F_DIM + x;
        t[threadIdx.y + j * 8][threadIdx.x] = __float2bfloat16(stoch_q(wr[idx], noise[idx], s));
    }
    __syncthreads();
#pragma unroll
    for (int j = 0; j < 4; j++) {
        int fo = blockIdx.x * 32 + threadIdx.y + j * 8;
        qoT[(size_t)fo * IN_DIM + y0 + threadIdx.x] = t[threadIdx.x][threadIdx.y + j * 8];
    }
}

// ===========================================================================
// Pipelined bf16 GEMM (HMMA): C(float) = A[4096x2048] @ B^T  (B stored [N][K])
// mma.sync.m16n8k16.bf16, CTA 128x128, 8 warps (2x4), warp tile 64x32,
// BK=64 elems (128B rows, SW128), 3-stage cp.async, 2 CTAs/SM.
// ===========================================================================
#define GBM 128
#define GBN 128
#define GBK 64
#define NSTAGE 3
#define KT (IN_DIM / GBK)                          // 32
#define STAGE_BYTES ((GBM + GBN) * GBK * 2)        // 32768
#define GEMM_SMEM (NSTAGE * STAGE_BYTES)           // 98304

__global__ __launch_bounds__(256, 2) void gemm_bf16_kernel(const __nv_bfloat16* __restrict__ A,
                                                           const __nv_bfloat16* __restrict__ Bm,
                                                           float* __restrict__ C) {
    extern __shared__ char smem[];
    uint32_t sb = smem_u32(smem);
    int tid = threadIdx.x, warp = tid >> 5, lane = tid & 31;
    int bm = blockIdx.y * GBM, bn = blockIdx.x * GBN;
    int wm = (warp >> 2) * 64;   // 2 warps along M
    int wn = (warp & 3) * 32;    // 4 warps along N

    float acc[4][4][4];
#pragma unroll
    for (int i = 0; i < 4; i++)
#pragma unroll
        for (int j = 0; j < 4; j++)
#pragma unroll
            for (int k = 0; k < 4; k++) acc[i][j][k] = 0.f;

    auto load_stage = [&](int s, int ki) {
        uint32_t sA = sb + s * STAGE_BYTES;
        uint32_t sB = sA + GBM * GBK * 2;
        int k0 = ki * GBK;
#pragma unroll
        for (int j = 0; j < 4; j++) {           // A: 128 rows x 8 x 16B = 1024 chunks
            int c = tid + j * 256;
            int row = c >> 3, cc = c & 7;
            cpasync16(sA + swz(row * 128 + cc * 16),
                      A + (size_t)(bm + row) * IN_DIM + k0 + cc * 8);
        }
#pragma unroll
        for (int j = 0; j < 4; j++) {           // B: 128 rows x 8 x 16B
            int c = tid + j * 256;
            int row = c >> 3, cc = c & 7;
            cpasync16(sB + swz(row * 128 + cc * 16),
                      Bm + (size_t)(bn + row) * IN_DIM + k0 + cc * 8);
        }
        asm volatile("cp.async.commit_group;\n");
    };

    load_stage(0, 0);
    load_stage(1, 1);

    int rl = lane & 15, chh = (lane >> 4) * 16;
    int cur = 0;
    for (int i = 0; i < KT; i++) {
        asm volatile("cp.async.wait_group 1;\n");   // stage i landed
        __syncthreads();                            // prev-iter reads done everywhere
        if (i + 2 < KT) {
            int nxt = cur + 2; if (nxt >= NSTAGE) nxt -= NSTAGE;
            load_stage(nxt, i + 2);                 // prefetch before compute
        }

        uint32_t sA = sb + cur * STAGE_BYTES;
        uint32_t sB = sA + GBM * GBK * 2;
#pragma unroll
        for (int ks = 0; ks < 4; ks++) {            // 4 x k16
            uint32_t a[4][4], b[2][4];
#pragma unroll
            for (int mt = 0; mt < 4; mt++)
                ldsm_x4(a[mt], sA + swz((wm + mt * 16 + rl) * 128 + ks * 32 + chh));
#pragma unroll
            for (int ng = 0; ng < 2; ng++)
                ldsm_x4(b[ng], sB + swz((wn + ng * 16 + rl) * 128 + ks * 32 + chh));
#pragma unroll
            for (int mt = 0; mt < 4; mt++)
#pragma unroll
                for (int ng = 0; ng < 2; ng++) {
                    mma_bf16(acc[mt][2 * ng + 0], a[mt], b[ng][0], b[ng][2]);
                    mma_bf16(acc[mt][2 * ng + 1], a[mt], b[ng][1], b[ng][3]);
                }
        }
        cur = (cur + 1 == NSTAGE) ? 0 : cur + 1;
    }

    // Epilogue: accumulators already float (exact ints), direct stores
    float* outp = C + (size_t)bm * F_DIM + bn;
#pragma unroll
    for (int mt = 0; mt < 4; mt++)
#pragma unroll
        for (int nt = 0; nt < 4; nt++) {
            int row = wm + mt * 16 + (lane >> 2);
            int col = wn + nt * 8 + (lane & 3) * 2;
            *(float2*)&outp[(size_t)row * F_DIM + col] =
                make_float2(acc[mt][nt][0], acc[mt][nt][1]);
            *(float2*)&outp[(size_t)(row + 8) * F_DIM + col] =
                make_float2(acc[mt][nt][2], acc[mt][nt][3]);
        }
}

// ===========================================================================
// Host launcher
// ===========================================================================
extern "C" void kernel_launch(void* const* d_in, const int* in_sizes, int n_in,
                              void* d_out, int out_size) {
    const float* x       = (const float*)d_in[0];  // [4096, 2048]
    const float* w       = (const float*)d_in[1];  // [2048, 4096]
    const float* bias    = (const float*)d_in[2];  // [4096]
    const float* noise_x = (const float*)d_in[5];  // [4096, 2048]
    const float* noise_w = (const float*)d_in[6];  // [2048, 4096]
    float* out = (float*)d_out;                    // [4096, 4096]

    float*          xr_p = nullptr;
    float*          wr_p = nullptr;
    __nv_bfloat16*  xq_p = nullptr;
    __nv_bfloat16*  wq_p = nullptr;
    float*          yr_p = nullptr;
    cudaGetSymbolAddress((void**)&xr_p, g_xr);
    cudaGetSymbolAddress((void**)&wr_p, g_wr);
    cudaGetSymbolAddress((void**)&xq_p, g_xq);
    cudaGetSymbolAddress((void**)&wq_p, g_wqT);
    cudaGetSymbolAddress((void**)&yr_p, g_yr);

    cudaFuncSetAttribute(gemm_bf16_kernel, cudaFuncAttributeMaxDynamicSharedMemorySize,
                         GEMM_SMEM);

    init_kernel<<<1, 1>>>();

    // xr = WHT_batch(x) (unnormalized), fused max on second pass
    colwht_kernel<1, false, false><<<(64 * IN_DIM) / 256, 256>>>(x, xr_p, IN_DIM, nullptr);
    colwht_kernel<64, true, false><<<(64 * IN_DIM) / 256, 256>>>(xr_p, xr_p, IN_DIM, nullptr);
    quantx_kernel<<<(B_DIM * IN_DIM / 4 + 255) / 256, 256>>>(xr_p, noise_x, xq_p,
                                                             B_DIM * IN_DIM / 4);

    // wr = WHT_features(w), fused max; quantize + transpose to [F][IN]
    rowwht_kernel<true><<<IN_DIM / 2, 128>>>(w, wr_p);
    quantw_transpose_kernel<<<dim3(F_DIM / 32, IN_DIM / 32), dim3(32, 8)>>>(wr_p, noise_w, wq_p);

    // pipelined bf16 HMMA GEMM -> float (exact integer arithmetic)
    gemm_bf16_kernel<<<dim3(F_DIM / GBN, B_DIM / GBM), 256, GEMM_SMEM>>>(xq_p, wq_p, yr_p);

    // inverse rotations: WHT along features (rows), then along batch (cols)
    rowwht_kernel<false><<<B_DIM / 2, 128>>>(yr_p, yr_p);
    colwht_kernel<1, false, false><<<(64 * F_DIM) / 256, 256>>>(yr_p, yr_p, F_DIM, nullptr);
    colwht_kernel<64, false, true><<<(64 * F_DIM) / 256, 256>>>(yr_p, out, F_DIM, bias);
}